// round 13
// baseline (speedup 1.0000x reference)
#include <cuda_runtime.h>
#include <math.h>

#define MAXDISP 192
#define NPAIR 2               // row-pairs per warp
#define RPW   (2 * NPAIR)     // 4 rows per warp

// Bijective monotone map: float bits -> uint32, uint compare == float compare.
__device__ __forceinline__ unsigned f2k(float f) {
    unsigned b = __float_as_uint(f);
    return b ^ (unsigned)(((int)b >> 31) | 0x80000000);
}
__device__ __forceinline__ float k2f(unsigned k) {
    unsigned t = (unsigned)((int)k >> 31);         // all-ones if orig positive
    return __uint_as_float(k ^ (~t | 0x80000000u));
}

struct Top2 { float v1, v2; unsigned c1, c2; };

// Sorted-pair helper: strict '>' keeps earlier slot on ties.
__device__ __forceinline__ Top2 pair2(float a, float b, unsigned sa, unsigned sb) {
    Top2 t;
    const bool g = b > a;
    t.v1 = fmaxf(a, b); t.v2 = fminf(a, b);
    t.c1 = g ? sb : sa; t.c2 = g ? sa : sb;
    return t;
}
// Merge two sorted top-2s; A must cover earlier columns (ties -> A side).
__device__ __forceinline__ Top2 merge2(const Top2 A, const Top2 B) {
    Top2 t;
    const bool m = B.v1 > A.v1;
    t.v1 = fmaxf(A.v1, B.v1);
    t.c1 = m ? B.c1 : A.c1;
    const float    sa = m ? A.v1 : A.v2;
    const unsigned ca = m ? A.c1 : A.c2;
    const float    sb = m ? B.v2 : B.v1;
    const unsigned cb = m ? B.c2 : B.c1;
    const bool h = sb > sa;
    t.v2 = fmaxf(sa, sb);
    t.c2 = h ? cb : ca;
    return t;
}
// Exact top-2 of one float4 (slots s..s+3, ascending columns).
__device__ __forceinline__ Top2 quad2(const float4 q, unsigned s) {
    return merge2(pair2(q.x, q.y, s, s + 1u), pair2(q.z, q.w, s + 2u, s + 3u));
}

__global__ __launch_bounds__(256, 6)
void disp_reg_kernel(const float* __restrict__ cost,
                     float* __restrict__ out,
                     int nrows)
{
    const int warp = (blockIdx.x * blockDim.x + threadIdx.x) >> 5;
    const int lane = threadIdx.x & 31;
    const int row0 = warp * RPW;
    if (row0 >= nrows) return;

    const unsigned gl   = (unsigned)(lane & 15);        // lane within half
    const unsigned half = (unsigned)(lane >> 4);        // 0: row A, 1: row B
    const unsigned hm   = 0xFFFFu << (lane & 16);       // half-warp mask

    // Per-row results stashed at lanes {bat} (rows 2*bat) and {16+bat}.
    unsigned rka = 0, rkb = 0, ri1 = 0, ri2 = 0;

#pragma unroll
    for (int bat = 0; bat < NPAIR; bat++) {
        // This lane's row: lanes 0-15 -> even row, 16-31 -> odd row.
        const float* rbase = cost
            + (size_t)(row0 + bat * 2 + half) * MAXDISP + gl * 4;

        // 3 x LDG.128: 12 elements covering columns gl*4 + {0..3,64..67,128..131}
        const float4 q0 = *(const float4*)(rbase);
        const float4 q1 = *(const float4*)(rbase + 64);
        const float4 q2 = *(const float4*)(rbase + 128);

        // Local exact top-2 of 12 (slot codes 0..11, ascending columns).
        const Top2 t = merge2(merge2(quad2(q0, 0u), quad2(q1, 4u)),
                              quad2(q2, 8u));

        // Half-warp collectives: one REDUX does both rows (partitioned mask).
        const unsigned k1 = f2k(t.v1);
        const unsigned t1 = __reduce_max_sync(hm, k1);
        // slot -> column: gl*4 + (s&3) + (s>>2)*64
        const unsigned col1 = gl * 4u + (t.c1 & 3u) + ((t.c1 >> 2) << 6);
        const unsigned gi1 = __reduce_min_sync(hm, (k1 == t1) ? col1 : 0xFFFFu);

        // Columns unique within a half-warp: col1==gi1 identifies the owner;
        // value-tied lanes keep v1 so exact ties propagate to rank 2.
        const bool own = (col1 == gi1);
        const float    cnd = own ? t.v2 : t.v1;
        const unsigned cs  = own ? t.c2 : t.c1;
        const unsigned k2  = f2k(cnd);
        const unsigned t2  = __reduce_max_sync(hm, k2);
        const unsigned col2 = gl * 4u + (cs & 3u) + ((cs >> 2) << 6);
        const unsigned gi2 = __reduce_min_sync(hm, (k2 == t2) ? col2 : 0xFFFFu);

        if (gl == (unsigned)bat) { rka = t1; rkb = t2; ri1 = gi1; ri2 = gi2; }
    }

    // Epilogue: lanes with gl < NPAIR finalize their rows
    // (lane bat -> row 2*bat, lane 16+bat -> row 2*bat+1).
    if (gl < NPAIR) {
        const int row = row0 + (int)gl * 2 + (int)half;
        if (row < nrows) {
            const float va = k2f(rka);
            const float vb = k2f(rkb);
            const float p = 1.0f / (1.0f + __expf(vb - va));
            out[row] = (float)ri1 * p + (float)ri2 * (1.0f - p);
        }
    }
}

extern "C" void kernel_launch(void* const* d_in, const int* in_sizes, int n_in,
                              void* d_out, int out_size)
{
    const float* cost = (const float*)d_in[0];
    float* out = (float*)d_out;

    const int nrows = in_sizes[0] / MAXDISP;   // 4 * 131072 = 524288

    const int threads = 256;                   // 8 warps/block, 32 rows/block
    const int rows_per_block = (threads / 32) * RPW;
    const int blocks = (nrows + rows_per_block - 1) / rows_per_block;

    disp_reg_kernel<<<blocks, threads>>>(cost, out, nrows);
}

// round 15
// speedup vs baseline: 1.1235x; 1.1235x over previous
#include <cuda_runtime.h>
#include <math.h>
#include <stdint.h>

#define MAXDISP     192
#define ROW_FLOATS  MAXDISP
#define CHUNK_ROWS  16
#define NCHUNK      4
#define CTA_ROWS    (CHUNK_ROWS * NCHUNK)          // 64 rows / CTA
#define CHUNK_FLOATS (CHUNK_ROWS * ROW_FLOATS)     // 3072
#define CHUNK_BYTES (CHUNK_FLOATS * 4)             // 12288
#define ROW_BYTES   (ROW_FLOATS * 4)               // 768

// Bijective monotone map: float bits -> uint32, uint compare == float compare.
__device__ __forceinline__ unsigned f2k(float f) {
    unsigned b = __float_as_uint(f);
    return b ^ (unsigned)(((int)b >> 31) | 0x80000000);
}
__device__ __forceinline__ float k2f(unsigned k) {
    unsigned t = (unsigned)((int)k >> 31);         // all-ones if orig positive
    return __uint_as_float(k ^ (~t | 0x80000000u));
}
// slot code s in 0..5 -> column = b0 + (s&1) + (s>>1)*64
__device__ __forceinline__ unsigned decode_col(unsigned b0, unsigned s) {
    return b0 + (s & 1u) + ((s >> 1) << 6);
}

#define MBAR_WAIT_P0(mbar_addr) do {                                         \
    unsigned _mb = (mbar_addr);                                              \
    asm volatile(                                                            \
        "{\n\t.reg .pred P1;\n\t"                                            \
        "WAIT_LOOP_%=:\n\t"                                                  \
        "mbarrier.try_wait.parity.acquire.cta.shared::cta.b64 P1, [%0], 0, 0x989680;\n\t" \
        "@P1 bra.uni WAIT_DONE_%=;\n\t"                                      \
        "bra.uni WAIT_LOOP_%=;\n\t"                                          \
        "WAIT_DONE_%=:\n\t}"                                                 \
        :: "r"(_mb) : "memory");                                             \
} while (0)

struct RowRes { unsigned ka, kb, i1, i2; };

// Exact top-2 of one row slice (6 values) + exact warp top-2 with
// lowest-column tie-break. All tie paths keep the earlier column.
__device__ __forceinline__ RowRes row_top2(const float2* dd, unsigned b0) {
    const float x0 = dd[0].x, x1 = dd[0].y;
    const float x2 = dd[1].x, x3 = dd[1].y;
    const float x4 = dd[2].x, x5 = dd[2].y;

    // Column-ordered pairs; strict '>' -> ties keep earlier slot.
    const bool g0 = x1 > x0;
    const float h0 = fmaxf(x0, x1), l0 = fminf(x0, x1);
    const unsigned s0h = g0 ? 1u : 0u, s0l = 1u - s0h;

    const bool g1 = x3 > x2;
    const float h1 = fmaxf(x2, x3), l1 = fminf(x2, x3);
    const unsigned s1h = g1 ? 3u : 2u, s1l = 5u - s1h;

    const bool g2 = x5 > x4;
    const float h2 = fmaxf(x4, x5), l2 = fminf(x4, x5);
    const unsigned s2h = g2 ? 5u : 4u, s2l = 9u - s2h;

    // merge(pair0, pair1): A = earlier columns; ties -> A side.
    float v1, v2; unsigned c1, c2;
    {
        const bool m = h1 > h0;
        v1 = fmaxf(h0, h1);
        c1 = m ? s1h : s0h;
        const float    sa = m ? h0  : l0;
        const unsigned ca = m ? s0h : s0l;
        const float    sb = m ? l1  : h1;
        const unsigned cb = m ? s1l : s1h;
        const bool h = sb > sa;
        v2 = fmaxf(sa, sb);
        c2 = h ? cb : ca;
    }
    // merge(M, pair2)
    {
        const bool m = h2 > v1;
        const float    nv1 = fmaxf(v1, h2);
        const unsigned nc1 = m ? s2h : c1;
        const float    sa = m ? v1 : v2;
        const unsigned ca = m ? c1 : c2;
        const float    sb = m ? l2  : h2;
        const unsigned cb = m ? s2l : s2h;
        const bool h = sb > sa;
        v2 = fmaxf(sa, sb);
        c2 = h ? cb : ca;
        v1 = nv1; c1 = nc1;
    }

    // Warp top-1 (exact value via bijective key).
    const unsigned k1 = f2k(v1);
    const unsigned t1 = __reduce_max_sync(0xFFFFFFFFu, k1);
    const unsigned col1 = decode_col(b0, c1);
    const unsigned gi1 = __reduce_min_sync(0xFFFFFFFFu,
                                           (k1 == t1) ? col1 : 0xFFFFu);

    // Columns are unique across lanes, so col1==gi1 identifies the single
    // owner; tied duplicate lanes keep v1 so exact ties reach rank 2.
    const bool own = (col1 == gi1);
    const float    cnd = own ? v2 : v1;
    const unsigned cc  = own ? c2 : c1;
    const unsigned k2 = f2k(cnd);
    const unsigned t2 = __reduce_max_sync(0xFFFFFFFFu, k2);
    const unsigned col2 = decode_col(b0, cc);
    const unsigned gi2 = __reduce_min_sync(0xFFFFFFFFu,
                                           (k2 == t2) ? col2 : 0xFFFFu);

    RowRes res; res.ka = t1; res.kb = t2; res.i1 = gi1; res.i2 = gi2;
    return res;
}

__global__ __launch_bounds__(256)
void disp_reg_kernel(const float* __restrict__ cost,
                     float* __restrict__ out,
                     int nrows)
{
    extern __shared__ float sbuf[];            // 4 x 12KB one-shot buffers
    __shared__ uint64_t mbar[NCHUNK];

    const int tid  = threadIdx.x;
    const int warp = tid >> 5;
    const int lane = tid & 31;
    const int cta_row0 = blockIdx.x * CTA_ROWS;

    // Init one mbarrier per chunk (single producer arrival via expect_tx).
    if (tid == 0) {
#pragma unroll
        for (int c = 0; c < NCHUNK; c++) {
            unsigned a = (unsigned)__cvta_generic_to_shared(&mbar[c]);
            asm volatile("mbarrier.init.shared.b64 [%0], %1;"
                         :: "r"(a), "r"(1u) : "memory");
        }
        // Order mbarrier.init (generic proxy) before TMA (async proxy) use.
        asm volatile("fence.proxy.async.shared::cta;" ::: "memory");
    }
    __syncthreads();

    // Producer: issue ALL chunk copies up front. The TMA engine keeps up to
    // 48KB/CTA in flight continuously -> DRAM demand is decoupled from the
    // consumer warps' compute schedule.
    if (tid == 0) {
#pragma unroll
        for (int c = 0; c < NCHUNK; c++) {
            const long long first = (long long)cta_row0 + c * CHUNK_ROWS;
            const long long rem   = (long long)nrows - first;
            if (rem <= 0) break;
            const unsigned bytes =
                (unsigned)((rem * ROW_BYTES < CHUNK_BYTES)
                               ? rem * ROW_BYTES : CHUNK_BYTES);
            const unsigned mb  = (unsigned)__cvta_generic_to_shared(&mbar[c]);
            const unsigned dst = (unsigned)__cvta_generic_to_shared(
                                     sbuf + c * CHUNK_FLOATS);
            const float* src = cost + first * ROW_FLOATS;
            asm volatile("mbarrier.arrive.expect_tx.shared.b64 _, [%0], %1;"
                         :: "r"(mb), "r"(bytes) : "memory");
            asm volatile(
                "cp.async.bulk.shared::cta.global.mbarrier::complete_tx::bytes"
                " [%0], [%1], %2, [%3];"
                :: "r"(dst), "l"(src), "r"(bytes), "r"(mb) : "memory");
        }
    }

    const unsigned b0 = (unsigned)(lane * 2);

    // Consumers: warp w handles rows {2w, 2w+1} of each 16-row chunk.
#pragma unroll
    for (int c = 0; c < NCHUNK; c++) {
        const int rowA = cta_row0 + c * CHUNK_ROWS + warp * 2;
        if (rowA >= nrows) break;

        {
            const unsigned mb = (unsigned)__cvta_generic_to_shared(&mbar[c]);
            MBAR_WAIT_P0(mb);
        }

        const float* chunk =
            sbuf + c * CHUNK_FLOATS + (warp * 2) * ROW_FLOATS;

        unsigned rka = 0, rkb = 0, ri1 = 0, ri2 = 0;
#pragma unroll
        for (int r = 0; r < 2; r++) {
            float2 d[3];
#pragma unroll
            for (int k = 0; k < 3; k++)
                d[k] = *(const float2*)(chunk + r * ROW_FLOATS + b0 + 64 * k);
            const RowRes res = row_top2(d, b0);
            if (lane == r) { rka = res.ka; rkb = res.kb;
                             ri1 = res.i1; ri2 = res.i2; }
        }

        if (lane < 2 && (rowA + lane) < nrows) {
            const float va = k2f(rka);
            const float vb = k2f(rkb);
            const float p = 1.0f / (1.0f + __expf(vb - va));
            out[rowA + lane] = (float)ri1 * p + (float)ri2 * (1.0f - p);
        }
    }
}

extern "C" void kernel_launch(void* const* d_in, const int* in_sizes, int n_in,
                              void* d_out, int out_size)
{
    const float* cost = (const float*)d_in[0];
    float* out = (float*)d_out;

    const int nrows = in_sizes[0] / MAXDISP;   // 4 * 131072 = 524288

    const int threads = 256;                   // 8 warps/CTA, 64 rows/CTA
    const int blocks = (nrows + CTA_ROWS - 1) / CTA_ROWS;   // 8192
    const int smem = NCHUNK * CHUNK_BYTES;     // 49152 B dynamic

    // Dynamic smem (48KB) + static mbar array exceeds the 48KB default
    // per-block budget -> opt in. Attribute set is host-side, idempotent,
    // capture-safe (not a stream operation, not an allocation).
    static bool attr_done = false;
    if (!attr_done) {
        cudaFuncSetAttribute(disp_reg_kernel,
                             cudaFuncAttributeMaxDynamicSharedMemorySize,
                             smem + 1024);
        attr_done = true;
    }

    disp_reg_kernel<<<blocks, threads, smem>>>(cost, out, nrows);
}